// round 5
// baseline (speedup 1.0000x reference)
#include <cuda_runtime.h>
#include <math.h>

#define DIM 128

__device__ __forceinline__ float sigmoidf_acc(float x) {
    return 1.0f / (1.0f + expf(-x));
}

__global__ void __launch_bounds__(256, 4)
gpf_kernel(const float* __restrict__ p, float* __restrict__ out, int nrows) {
    // 8 lanes per row, 4 rows per warp.
    const int tid   = blockIdx.x * blockDim.x + threadIdx.x;
    const int gwarp = tid >> 5;
    if (gwarp * 4 >= nrows) return;          // warp-uniform guard
    const int g = (threadIdx.x >> 3) & 3;    // row-group within warp (0..3)
    const int s = threadIdx.x & 7;           // sub-lane within row   (0..7)
    const int row  = gwarp * 4 + g;
    const int rowc = row < nrows ? row : nrows - 1;

    // float4 view; one row = 5*128 floats = 160 float4
    const float4* pv = reinterpret_cast<const float4*>(p);
    const int b4 = rowc * 160 + s;           // fits in int (max ~42M)

    // 15 Gram accumulators, pairs (i,j) i<=j upper-triangular order
    float acc[15];
#pragma unroll
    for (int k = 0; k < 15; k++) acc[k] = 0.0f;

    // Stream 4 chunks of 8 float4 per vertex; lane s owns float4 (c*8+s).
#pragma unroll
    for (int c = 0; c < 4; c++) {
        float4 v[5];
#pragma unroll
        for (int i = 0; i < 5; i++) v[i] = pv[b4 + i * 32 + c * 8];
        int idx = 0;
#pragma unroll
        for (int i = 0; i < 5; i++)
#pragma unroll
            for (int j = i; j < 5; j++) {
                acc[idx] += v[i].x * v[j].x + v[i].y * v[j].y +
                            v[i].z * v[j].z + v[i].w * v[j].w;
                idx++;
            }
    }

    // Butterfly over the 8 lanes of this row-group (offsets 4,2,1 stay in-group).
#pragma unroll
    for (int off = 4; off > 0; off >>= 1) {
#pragma unroll
        for (int k = 0; k < 15; k++)
            acc[k] += __shfl_xor_sync(0xffffffffu, acc[k], off);
    }

    // ---------------- per-row epilogue (8-way redundant per group) ----------
    const float sq0 = acc[0],  sq1 = acc[5],  sq2 = acc[9], sq3 = acc[12], sq4 = acc[14];
    const float g01 = acc[1],  g02 = acc[2],  g03 = acc[3], g04 = acc[4];
    const float g12 = acc[6],  g13 = acc[7],  g14 = acc[8];
    const float g23 = acc[10], g24 = acc[11];
    const float g34 = acc[13];

    // 10 squared edges, triu(k=1) order: 01,02,03,04,12,13,14,23,24,34
    const float a = fmaxf(sq0 + sq1 - 2.0f * g01, 0.0f);
    const float b = fmaxf(sq0 + sq2 - 2.0f * g02, 0.0f);
    const float c = fmaxf(sq0 + sq3 - 2.0f * g03, 0.0f);
    const float d = fmaxf(sq0 + sq4 - 2.0f * g04, 0.0f);
    const float e = fmaxf(sq1 + sq2 - 2.0f * g12, 0.0f);
    const float f = fmaxf(sq1 + sq3 - 2.0f * g13, 0.0f);
    const float gg = fmaxf(sq1 + sq4 - 2.0f * g14, 0.0f);
    const float h = fmaxf(sq2 + sq3 - 2.0f * g23, 0.0f);
    const float i_ = fmaxf(sq2 + sq4 - 2.0f * g24, 0.0f);
    const float j = fmaxf(sq3 + sq4 - 2.0f * g34, 0.0f);

    // Edge statistics (ddof=1)
    const float e0 = sqrtf(a), e1 = sqrtf(b), e2 = sqrtf(c), e3 = sqrtf(d);
    const float e4 = sqrtf(e), e5 = sqrtf(f), e6 = sqrtf(gg), e7 = sqrtf(h);
    const float e8 = sqrtf(i_), e9 = sqrtf(j);
    const float mean_edge = (e0 + e1 + e2 + e3 + e4 + e5 + e6 + e7 + e8 + e9) * 0.1f;
    float evar = 0.0f;
    {
        float t;
        t = e0 - mean_edge; evar += t * t;  t = e1 - mean_edge; evar += t * t;
        t = e2 - mean_edge; evar += t * t;  t = e3 - mean_edge; evar += t * t;
        t = e4 - mean_edge; evar += t * t;  t = e5 - mean_edge; evar += t * t;
        t = e6 - mean_edge; evar += t * t;  t = e7 - mean_edge; evar += t * t;
        t = e8 - mean_edge; evar += t * t;  t = e9 - mean_edge; evar += t * t;
    }
    const float std_edge = sqrtf(evar / 9.0f);

    // Vertex spread from Gram: |p_i - cen|^2 = sq_i - 0.4*s_i + 0.04*S,
    // s_i = sum_j g_ij (incl. diagonal), S = sum s_i.
    const float s0 = sq0 + g01 + g02 + g03 + g04;
    const float s1 = g01 + sq1 + g12 + g13 + g14;
    const float s2 = g02 + g12 + sq2 + g23 + g24;
    const float s3 = g03 + g13 + g23 + sq3 + g34;
    const float s4 = g04 + g14 + g24 + g34 + sq4;
    const float S  = s0 + s1 + s2 + s3 + s4;
    const float q  = 0.04f * S;
    const float dc0 = sqrtf(fmaxf(sq0 - 0.4f * s0 + q, 0.0f));
    const float dc1 = sqrtf(fmaxf(sq1 - 0.4f * s1 + q, 0.0f));
    const float dc2 = sqrtf(fmaxf(sq2 - 0.4f * s2 + q, 0.0f));
    const float dc3 = sqrtf(fmaxf(sq3 - 0.4f * s3 + q, 0.0f));
    const float dc4 = sqrtf(fmaxf(sq4 - 0.4f * s4 + q, 0.0f));
    const float mean_dc = (dc0 + dc1 + dc2 + dc3 + dc4) * 0.2f;
    float svar = 0.0f;
    {
        float t;
        t = dc0 - mean_dc; svar += t * t;  t = dc1 - mean_dc; svar += t * t;
        t = dc2 - mean_dc; svar += t * t;  t = dc3 - mean_dc; svar += t * t;
        t = dc4 - mean_dc; svar += t * t;
    }
    const float spread = sqrtf(svar / 4.0f);

    // Cayley-Menger determinant via symbolic reduction to a symmetric 4x4:
    // det M = -det C with
    //   C = [[-2a, E, F, G],[E,-2b,H,I],[F,H,-2c,J],[G,I,J,-2d]]
    //   E=e-a-b F=f-a-c G=g-a-d H=h-b-c I=i-b-d J=j-c-d
    // vol_sq = det C / 9216  (sign verified on the regular simplex).
    const float E = e  - a - b;
    const float F = f  - a - c;
    const float G = gg - a - d;
    const float H = h  - b - c;
    const float I = i_ - b - d;
    const float J = j  - c - d;
    float c11 = -2.0f * b, c12 = H, c13 = I;
    float c22 = -2.0f * c, c23 = J;
    float c33 = -2.0f * d;
    const float p0 = -2.0f * a;
    {
        const float r0  = 1.0f / p0;
        const float l10 = E * r0, l20 = F * r0, l30 = G * r0;
        c11 -= l10 * E;  c12 -= l10 * F;  c13 -= l10 * G;
        c22 -= l20 * F;  c23 -= l20 * G;
        c33 -= l30 * G;
    }
    const float p1 = c11;
    {
        const float r1  = 1.0f / p1;
        const float l21 = c12 * r1, l31 = c13 * r1;
        c22 -= l21 * c12;  c23 -= l21 * c13;
        c33 -= l31 * c13;
    }
    const float p2 = c22;
    {
        const float r2  = 1.0f / p2;
        const float l32 = c23 * r2;
        c33 -= l32 * c23;
    }
    const float detC = p0 * p1 * p2 * c33;
    const float vol_sq = fmaxf(detC / 9216.0f, 0.0f);
    const float volume = sqrtf(vol_sq);

    // Seed
    const float seed = sigmoidf_acc(volume * 10.0f) * 0.4f
                     + sigmoidf_acc(std_edge / (mean_edge + 1e-6f)) * 0.3f
                     + sigmoidf_acc(spread) * 0.3f;

    float x = fminf(fmaxf(seed, 1e-6f), 1.0f - 1e-6f);

    // Ternary Cantor digit extraction, depth 8
    float cantor = 0.0f;
    float factor = 0.5f;
#pragma unroll
    for (int it = 0; it < 8; it++) {
        const float xs = x * 3.0f;
        const int   dg = (int)xs;            // trunc == floor (xs >= 0)
        x = xs - (float)dg;
        if (dg == 2) cantor += factor;
        factor *= 0.5f;
    }
    cantor = fminf(fmaxf(cantor, 0.0f), 1.0f);

    if (s == 0 && row < nrows) out[row] = cantor;
}

extern "C" void kernel_launch(void* const* d_in, const int* in_sizes, int n_in,
                              void* d_out, int out_size) {
    const float* p = (const float*)d_in[0];
    float* out = (float*)d_out;
    const int nrows = in_sizes[0] / (5 * DIM);   // 262144
    // 256 threads = 8 warps = 32 rows per block
    const int rows_per_block = 32;
    const int blocks = (nrows + rows_per_block - 1) / rows_per_block;
    gpf_kernel<<<blocks, 256>>>(p, out, nrows);
}

// round 7
// speedup vs baseline: 1.0162x; 1.0162x over previous
#include <cuda_runtime.h>
#include <math.h>

#define DIM 128

__device__ __forceinline__ float sigmoidf_acc(float x) {
    return 1.0f / (1.0f + expf(-x));
}

__global__ void __launch_bounds__(256, 4)
gpf_kernel(const float* __restrict__ p, float* __restrict__ out, int nrows) {
    // 8 lanes per row, 4 rows per warp.
    const int tid   = blockIdx.x * blockDim.x + threadIdx.x;
    const int gwarp = tid >> 5;
    if (gwarp * 4 >= nrows) return;          // warp-uniform guard
    const int g = (threadIdx.x >> 3) & 3;    // row-group within warp (0..3)
    const int s = threadIdx.x & 7;           // sub-lane within row   (0..7)
    const int row  = gwarp * 4 + g;
    const int rowc = row < nrows ? row : nrows - 1;

    // float4 view; one row = 5*128 floats = 160 float4
    const float4* pv = reinterpret_cast<const float4*>(p);
    const int b4 = rowc * 160 + s;           // fits in int (max ~42M)

    // 15 Gram accumulators, pairs (i,j) i<=j upper-triangular order
    float acc[15];
#pragma unroll
    for (int k = 0; k < 15; k++) acc[k] = 0.0f;

    // Stream 4 chunks of 8 float4 per vertex; lane s owns float4 (c*8+s).
#pragma unroll
    for (int c = 0; c < 4; c++) {
        float4 v[5];
#pragma unroll
        for (int i = 0; i < 5; i++) v[i] = pv[b4 + i * 32 + c * 8];
        int idx = 0;
#pragma unroll
        for (int i = 0; i < 5; i++)
#pragma unroll
            for (int j = i; j < 5; j++) {
                acc[idx] += v[i].x * v[j].x + v[i].y * v[j].y +
                            v[i].z * v[j].z + v[i].w * v[j].w;
                idx++;
            }
    }

    // Butterfly over the 8 lanes of this row-group (offsets 4,2,1 stay in-group).
#pragma unroll
    for (int off = 4; off > 0; off >>= 1) {
#pragma unroll
        for (int k = 0; k < 15; k++)
            acc[k] += __shfl_xor_sync(0xffffffffu, acc[k], off);
    }

    // ---------------- per-row epilogue (8-way redundant per group) ----------
    const float sq0 = acc[0],  sq1 = acc[5],  sq2 = acc[9], sq3 = acc[12], sq4 = acc[14];
    const float g01 = acc[1],  g02 = acc[2],  g03 = acc[3], g04 = acc[4];
    const float g12 = acc[6],  g13 = acc[7],  g14 = acc[8];
    const float g23 = acc[10], g24 = acc[11];
    const float g34 = acc[13];

    // 10 squared edges, triu(k=1) order: 01,02,03,04,12,13,14,23,24,34
    const float a = fmaxf(sq0 + sq1 - 2.0f * g01, 0.0f);
    const float b = fmaxf(sq0 + sq2 - 2.0f * g02, 0.0f);
    const float c = fmaxf(sq0 + sq3 - 2.0f * g03, 0.0f);
    const float d = fmaxf(sq0 + sq4 - 2.0f * g04, 0.0f);
    const float e = fmaxf(sq1 + sq2 - 2.0f * g12, 0.0f);
    const float f = fmaxf(sq1 + sq3 - 2.0f * g13, 0.0f);
    const float gg = fmaxf(sq1 + sq4 - 2.0f * g14, 0.0f);
    const float h = fmaxf(sq2 + sq3 - 2.0f * g23, 0.0f);
    const float i_ = fmaxf(sq2 + sq4 - 2.0f * g24, 0.0f);
    const float j = fmaxf(sq3 + sq4 - 2.0f * g34, 0.0f);

    // Edge statistics (ddof=1)
    const float e0 = sqrtf(a), e1 = sqrtf(b), e2 = sqrtf(c), e3 = sqrtf(d);
    const float e4 = sqrtf(e), e5 = sqrtf(f), e6 = sqrtf(gg), e7 = sqrtf(h);
    const float e8 = sqrtf(i_), e9 = sqrtf(j);
    const float mean_edge = (e0 + e1 + e2 + e3 + e4 + e5 + e6 + e7 + e8 + e9) * 0.1f;
    float evar = 0.0f;
    {
        float t;
        t = e0 - mean_edge; evar += t * t;  t = e1 - mean_edge; evar += t * t;
        t = e2 - mean_edge; evar += t * t;  t = e3 - mean_edge; evar += t * t;
        t = e4 - mean_edge; evar += t * t;  t = e5 - mean_edge; evar += t * t;
        t = e6 - mean_edge; evar += t * t;  t = e7 - mean_edge; evar += t * t;
        t = e8 - mean_edge; evar += t * t;  t = e9 - mean_edge; evar += t * t;
    }
    const float std_edge = sqrtf(evar / 9.0f);

    // Vertex spread from Gram: |p_i - cen|^2 = sq_i - 0.4*s_i + 0.04*S,
    // s_i = sum_j g_ij (incl. diagonal), S = sum s_i.
    const float s0 = sq0 + g01 + g02 + g03 + g04;
    const float s1 = g01 + sq1 + g12 + g13 + g14;
    const float s2 = g02 + g12 + sq2 + g23 + g24;
    const float s3 = g03 + g13 + g23 + sq3 + g34;
    const float s4 = g04 + g14 + g24 + g34 + sq4;
    const float S  = s0 + s1 + s2 + s3 + s4;
    const float q  = 0.04f * S;
    const float dc0 = sqrtf(fmaxf(sq0 - 0.4f * s0 + q, 0.0f));
    const float dc1 = sqrtf(fmaxf(sq1 - 0.4f * s1 + q, 0.0f));
    const float dc2 = sqrtf(fmaxf(sq2 - 0.4f * s2 + q, 0.0f));
    const float dc3 = sqrtf(fmaxf(sq3 - 0.4f * s3 + q, 0.0f));
    const float dc4 = sqrtf(fmaxf(sq4 - 0.4f * s4 + q, 0.0f));
    const float mean_dc = (dc0 + dc1 + dc2 + dc3 + dc4) * 0.2f;
    float svar = 0.0f;
    {
        float t;
        t = dc0 - mean_dc; svar += t * t;  t = dc1 - mean_dc; svar += t * t;
        t = dc2 - mean_dc; svar += t * t;  t = dc3 - mean_dc; svar += t * t;
        t = dc4 - mean_dc; svar += t * t;
    }
    const float spread = sqrtf(svar / 4.0f);

    // Cayley-Menger determinant via symbolic reduction to a symmetric 4x4:
    // det M = -det C with
    //   C = [[-2a, E, F, G],[E,-2b,H,I],[F,H,-2c,J],[G,I,J,-2d]]
    //   E=e-a-b F=f-a-c G=g-a-d H=h-b-c I=i-b-d J=j-c-d
    // vol_sq = det C / 9216  (sign verified on the regular simplex).
    const float E = e  - a - b;
    const float F = f  - a - c;
    const float G = gg - a - d;
    const float H = h  - b - c;
    const float I = i_ - b - d;
    const float J = j  - c - d;
    float c11 = -2.0f * b, c12 = H, c13 = I;
    float c22 = -2.0f * c, c23 = J;
    float c33 = -2.0f * d;
    const float p0 = -2.0f * a;
    {
        const float r0  = 1.0f / p0;
        const float l10 = E * r0, l20 = F * r0, l30 = G * r0;
        c11 -= l10 * E;  c12 -= l10 * F;  c13 -= l10 * G;
        c22 -= l20 * F;  c23 -= l20 * G;
        c33 -= l30 * G;
    }
    const float p1 = c11;
    {
        const float r1  = 1.0f / p1;
        const float l21 = c12 * r1, l31 = c13 * r1;
        c22 -= l21 * c12;  c23 -= l21 * c13;
        c33 -= l31 * c13;
    }
    const float p2 = c22;
    {
        const float r2  = 1.0f / p2;
        const float l32 = c23 * r2;
        c33 -= l32 * c23;
    }
    const float detC = p0 * p1 * p2 * c33;
    const float vol_sq = fmaxf(detC / 9216.0f, 0.0f);
    const float volume = sqrtf(vol_sq);

    // Seed
    const float seed = sigmoidf_acc(volume * 10.0f) * 0.4f
                     + sigmoidf_acc(std_edge / (mean_edge + 1e-6f)) * 0.3f
                     + sigmoidf_acc(spread) * 0.3f;

    float x = fminf(fmaxf(seed, 1e-6f), 1.0f - 1e-6f);

    // Ternary Cantor digit extraction, depth 8
    float cantor = 0.0f;
    float factor = 0.5f;
#pragma unroll
    for (int it = 0; it < 8; it++) {
        const float xs = x * 3.0f;
        const int   dg = (int)xs;            // trunc == floor (xs >= 0)
        x = xs - (float)dg;
        if (dg == 2) cantor += factor;
        factor *= 0.5f;
    }
    cantor = fminf(fmaxf(cantor, 0.0f), 1.0f);

    if (s == 0 && row < nrows) out[row] = cantor;
}

extern "C" void kernel_launch(void* const* d_in, const int* in_sizes, int n_in,
                              void* d_out, int out_size) {
    const float* p = (const float*)d_in[0];
    float* out = (float*)d_out;
    const int nrows = in_sizes[0] / (5 * DIM);   // 262144
    // 256 threads = 8 warps = 32 rows per block
    const int rows_per_block = 32;
    const int blocks = (nrows + rows_per_block - 1) / rows_per_block;
    gpf_kernel<<<blocks, 256>>>(p, out, nrows);
}